// round 8
// baseline (speedup 1.0000x reference)
#include <cuda_runtime.h>
#include <cuda_bf16.h>
#include <cstdint>

// Problem constants (fixed shapes)
static constexpr int B_   = 64;
static constexpr int N_   = 2048;
static constexpr int D_   = 128;
static constexpr int K_   = 1024;          // ceil(0.5 * N)
static constexpr int BN_  = B_ * N_;       // 131072 nodes
static constexpr int BK_  = B_ * K_;       // 65536 kept nodes
static constexpr int EPG_ = N_ * 32;       // 65536 edges per graph
static constexpr int NPC_ = 8;             // CTAs per graph (deg & scatter)
static constexpr int EPC_ = EPG_ / NPC_;   // 8192 edges per CTA
static constexpr int NCTA_ = B_ * NPC_;    // 512

// fixed-point encoding: per-edge add  llround((m+16)*2^40) + (1<<56)
//   low 56 bits : sum of (m+16)*2^40  (positive, < 2^53 total)
//   bits 56..63 : indeg count (< 256)
static constexpr unsigned long long TAG_  = 1ULL << 56;
static constexpr unsigned long long MASK_ = TAG_ - 1ULL;

// backend grid layout
static constexpr int FULL_B_ = BN_ / 32;          // 4096 full-emit blocks
static constexpr int PERM_B_ = 2 * BK_ / 32;      // 4096 perm-emit blocks

// ---------------- scratch (device globals; no allocation allowed) ----------
__device__ int                g_out[BN_];     // outdeg (global atomic merge)
__device__ unsigned long long g_spu2[BN_];    // fused sum+indeg (atomic merge)
__device__ float2             g_s[BN_];       // dot product (hi, lo)
__device__ float  g_score[BN_];
__device__ float  g_t[BN_];
__device__ int    g_perm[BK_];                // kept rows    (global ids)
__device__ int    g_permc[BK_];               // dropped rows (global ids)
__device__ int    g_done[B_];                 // per-graph sort-complete flag
__device__ float  g_sumexp;

// monotonic float->uint mapping (for sort keys)
__device__ __forceinline__ unsigned int ford(float f) {
    unsigned int u = __float_as_uint(f);
    return (u & 0x80000000u) ? ~u : (u | 0x80000000u);
}

// error-free addition: s + e == a + b exactly.
__device__ __forceinline__ void two_sum(float a, float b, float& s, float& e) {
    float s_ = a + b;
    float bb = s_ - a;
    e = (a - (s_ - bb)) + (b - bb);
    s = s_;
}

// ---------------- kernels ---------------------------------------------------

__global__ void init_kernel() {
    int i = blockIdx.x * blockDim.x + threadIdx.x;
    if (i < BN_) { g_out[i] = 0; g_spu2[i] = 0ULL; }
    if (i < B_)  g_done[i] = 0;
    if (i == 0)  g_sumexp = 0.0f;
}

// Grid-fused: blocks [0,512)   = src histogram -> global atomic merge;
//             blocks [512,1024) = compensated dot (DRAM bound).
__global__ __launch_bounds__(256) void degdot_kernel(const int* __restrict__ src,
                                                     const float* __restrict__ feat,
                                                     const float* __restrict__ W) {
    const int tid = threadIdx.x;
    if (blockIdx.x < NCTA_) {
        // ---- deg path ----
        __shared__ int h[N_];
        const int c = blockIdx.x;
        const int g = c >> 3, sub = c & 7;
        for (int i = tid; i < N_; i += 256) h[i] = 0;
        __syncthreads();
        const int4* p = reinterpret_cast<const int4*>(src + g * EPG_ + sub * EPC_);
        #pragma unroll
        for (int it = 0; it < EPC_ / (256 * 4); ++it) {
            int4 v = p[tid + it * 256];
            atomicAdd(&h[v.x & (N_ - 1)], 1);
            atomicAdd(&h[v.y & (N_ - 1)], 1);
            atomicAdd(&h[v.z & (N_ - 1)], 1);
            atomicAdd(&h[v.w & (N_ - 1)], 1);
        }
        __syncthreads();
        for (int i = tid; i < N_; i += 256)
            atomicAdd(&g_out[g * N_ + i], h[i]);
    } else {
        // ---- dot path: 8 warps x 32 rows each ----
        const int c2   = blockIdx.x - NCTA_;          // 0..511
        const int wip  = tid >> 5;
        const int lane = tid & 31;
        const int row0 = c2 * 256 + wip * 32;
        const float4 wv = __ldg(reinterpret_cast<const float4*>(W) + lane);
        for (int i = 0; i < 32; ++i) {
            int w = row0 + i;
            float4 f = __ldg(reinterpret_cast<const float4*>(feat) + (size_t)w * 32 + lane);
            float p0 = f.x * wv.x, e0 = fmaf(f.x, wv.x, -p0);
            float p1 = f.y * wv.y, e1 = fmaf(f.y, wv.y, -p1);
            float p2 = f.z * wv.z, e2 = fmaf(f.z, wv.z, -p2);
            float p3 = f.w * wv.w, e3 = fmaf(f.w, wv.w, -p3);
            float hi, lo, err;
            two_sum(p0, p1, hi, lo);
            two_sum(hi, p2, hi, err); lo += err;
            two_sum(hi, p3, hi, err); lo += err;
            lo += (e0 + e1) + (e2 + e3);
            #pragma unroll
            for (int o = 16; o > 0; o >>= 1) {
                float h2 = __shfl_xor_sync(0xFFFFFFFFu, hi, o);
                float l2 = __shfl_xor_sync(0xFFFFFFFFu, lo, o);
                two_sum(hi, h2, hi, err);
                lo += l2 + err;
            }
            if (lane == 0) g_s[w] = make_float2(hi, lo);
        }
    }
}

// Scatter: build messages in-CTA (rsqrt table), stage in SMEM, one u64 SMEM
// atomic per edge, flush via global u64 atomicAdd (exact integer merge).
__global__ __launch_bounds__(256) void scatter_kernel(const int* __restrict__ src,
                                                      const int* __restrict__ dst) {
    __shared__ double rsqd[256];             // 2KB
    __shared__ unsigned long long acc[N_];   // 16KB
    __shared__ unsigned long long msg[N_];   // 16KB
    const int c = blockIdx.x;
    const int g = c >> 3, sub = c & 7;
    const int tid = threadIdx.x;
    const int gb = g * N_;

    rsqd[tid] = 1.0 / sqrt((double)(tid < 1 ? 1 : tid));
    for (int i = tid; i < N_; i += 256) acc[i] = 0ULL;
    __syncthreads();

    for (int i = tid; i < N_; i += 256) {
        int od = g_out[gb + i];
        od = od < 1 ? 1 : (od > 255 ? 255 : od);
        float2 s2 = g_s[gb + i];
        double s = (double)s2.x + (double)s2.y;
        double m = s * rsqd[od];
        msg[i] = (unsigned long long)llround((m + 16.0) * 0x1p40) + TAG_;
    }
    __syncthreads();

    const int4* ps = reinterpret_cast<const int4*>(src + g * EPG_ + sub * EPC_);
    const int4* pd = reinterpret_cast<const int4*>(dst + g * EPG_ + sub * EPC_);
    #pragma unroll
    for (int it = 0; it < EPC_ / (256 * 4); ++it) {
        int4 s4 = ps[tid + it * 256];
        int4 d4 = pd[tid + it * 256];
        atomicAdd(&acc[d4.x & (N_ - 1)], msg[s4.x & (N_ - 1)]);
        atomicAdd(&acc[d4.y & (N_ - 1)], msg[s4.y & (N_ - 1)]);
        atomicAdd(&acc[d4.z & (N_ - 1)], msg[s4.z & (N_ - 1)]);
        atomicAdd(&acc[d4.w & (N_ - 1)], msg[s4.w & (N_ - 1)]);
    }
    __syncthreads();
    for (int i = tid; i < N_; i += 256)
        atomicAdd(&g_spu2[gb + i], acc[i]);
}

// Decode merged u64; score = sum*rsqrt(indeg) + b; t = tanh; sumexp reduce.
__global__ __launch_bounds__(256) void finalize_kernel(const float* __restrict__ b) {
    __shared__ double rsqd[256];
    __shared__ float sm[32];
    const int tid = threadIdx.x;
    rsqd[tid] = 1.0 / sqrt((double)(tid < 1 ? 1 : tid));
    __syncthreads();

    int v = blockIdx.x * blockDim.x + tid;
    float e = 0.0f;
    if (v < BN_) {
        unsigned long long a = g_spu2[v];
        int id = (int)(a >> 56);
        double sum = (double)(a & MASK_) * 0x1p-40 - 16.0 * (double)id;
        double sd = sum * rsqd[id < 1 ? 1 : id] + (double)__ldg(b);
        float sc = (float)sd;
        g_score[v] = sc;
        g_t[v] = tanhf(sc);
        e = __expf(sc);
    }
    #pragma unroll
    for (int o = 16; o > 0; o >>= 1) e += __shfl_xor_sync(0xFFFFFFFFu, e, o);
    int lane = tid & 31, wid = tid >> 5;
    if (lane == 0) sm[wid] = e;
    __syncthreads();
    if (wid == 0) {
        e = (lane < (blockDim.x >> 5)) ? sm[lane] : 0.0f;
        #pragma unroll
        for (int o = 16; o > 0; o >>= 1) e += __shfl_xor_sync(0xFFFFFFFFu, e, o);
        if (lane == 0) atomicAdd(&g_sumexp, e);
    }
}

// register-phase bitonic compare-exchange (j <= 16, within warp)
__device__ __forceinline__ void reg_ex(unsigned long long& key, int i, int j, int k) {
    unsigned long long p = __shfl_xor_sync(0xFFFFFFFFu, key, j);
    bool up  = ((i & k) == 0);
    bool low = ((i & j) == 0);
    unsigned long long mn = key < p ? key : p;
    unsigned long long mx = key < p ? p : key;
    key = (low == up) ? mn : mx;
}

// Backend: blocks [0,64)            = per-graph sort -> perms, then set flag;
//          blocks [64, 64+4096)     = emit feature_full + score_sm;
//          blocks [4160, 4160+4096) = flag-gated dist/com emit (gather feature).
__global__ __launch_bounds__(1024, 2) void backend_kernel(const float* __restrict__ feat,
                                                          float* __restrict__ out_perm,
                                                          float* __restrict__ out_perm_com,
                                                          float* __restrict__ out_full,
                                                          float* __restrict__ out_sm,
                                                          float* __restrict__ out_dist,
                                                          float* __restrict__ out_com) {
    __shared__ unsigned long long keys[N_];
    __shared__ int flags[N_];
    __shared__ int woff[33];

    const int tid  = threadIdx.x;
    const int bid  = blockIdx.x;
    const int warp = tid >> 5;
    const int lane = tid & 31;

    if (bid >= B_ && bid < B_ + FULL_B_) {
        // ---- full-emit path: one warp per node row ----
        int w = (bid - B_) * 32 + warp;
        float t = g_t[w];
        float4 f = __ldg(reinterpret_cast<const float4*>(feat) + (size_t)w * 32 + lane);
        f.x *= t; f.y *= t; f.z *= t; f.w *= t;
        reinterpret_cast<float4*>(out_full + (size_t)w * D_)[lane] = f;
        if (lane == 0) out_sm[w] = __expf(g_score[w]) / g_sumexp;
        return;
    }

    if (bid >= B_ + FULL_B_) {
        // ---- perm-emit path: wait for this graph's sort, then 32 rows ----
        int pid = bid - (B_ + FULL_B_);
        int g = pid >> 6, c = pid & 63;
        if (tid == 0) {
            while (atomicAdd(&g_done[g], 0) == 0) __nanosleep(100);
        }
        __syncthreads();
        int p; float* o;
        if (c < 32) {
            int row = g * K_ + c * 32 + warp;
            p = g_perm[row];
            o = out_dist + (size_t)row * D_;
        } else {
            int row = g * K_ + (c - 32) * 32 + warp;
            p = g_permc[row];
            o = out_com + (size_t)row * D_;
        }
        float t = g_t[p];
        float4 f = __ldg(reinterpret_cast<const float4*>(feat) + (size_t)p * 32 + lane);
        f.x *= t; f.y *= t; f.z *= t; f.w *= t;
        reinterpret_cast<float4*>(o)[lane] = f;
        return;
    }

    // ---- sort path ----
    const int g    = bid;
    const int base = g * N_;
    const int i0 = tid, i1 = tid + 1024;

    unsigned long long k0, k1;
    {
        unsigned int a = ~ford(g_score[base + i0]);
        unsigned int b = ~ford(g_score[base + i1]);
        k0 = ((unsigned long long)a << 32) | (unsigned int)i0;
        k1 = ((unsigned long long)b << 32) | (unsigned int)i1;
    }

    // k = 2..32 entirely in registers
    #pragma unroll
    for (int k = 2; k <= 32; k <<= 1)
        for (int j = k >> 1; j >= 1; j >>= 1) { reg_ex(k0, i0, j, k); reg_ex(k1, i1, j, k); }

    // k = 64..2048: SMEM passes for j>=32, register passes for j<=16
    for (int k = 64; k <= N_; k <<= 1) {
        keys[i0] = k0; keys[i1] = k1;
        __syncthreads();
        for (int j = k >> 1; j >= 32; j >>= 1) {
            #pragma unroll
            for (int r = 0; r < 2; r++) {
                int i = tid + r * 1024;
                int ixj = i ^ j;
                if (ixj > i) {
                    unsigned long long a = keys[i], c = keys[ixj];
                    bool up = ((i & k) == 0);
                    if ((a > c) == up) { keys[i] = c; keys[ixj] = a; }
                }
            }
            __syncthreads();
        }
        k0 = keys[i0]; k1 = keys[i1];
        #pragma unroll
        for (int j = 16; j >= 1; j >>= 1) { reg_ex(k0, i0, j, k); reg_ex(k1, i1, j, k); }
    }
    keys[i0] = k0; keys[i1] = k1;
    __syncthreads();

    // flags: 1 = unselected
    flags[i0] = 1; flags[i1] = 1;
    __syncthreads();

    // top K_ = first 1024 sorted entries
    {
        int local = (int)(unsigned int)(keys[tid] & 0xFFFFFFFFull);
        flags[local] = 0;
        int gid = base + local;
        g_perm[g * K_ + tid]   = gid;
        out_perm[g * K_ + tid] = (float)gid;
    }
    __syncthreads();

    // warp-shfl scan over contiguous pairs
    {
        int e0 = 2 * tid, e1 = 2 * tid + 1;
        int f0 = flags[e0], f1 = flags[e1];
        int v = f0 + f1;
        int sv = v;
        #pragma unroll
        for (int o = 1; o < 32; o <<= 1) {
            int n = __shfl_up_sync(0xFFFFFFFFu, sv, o);
            if ((tid & 31) >= o) sv += n;
        }
        if ((tid & 31) == 31) woff[(tid >> 5) + 1] = sv;
        __syncthreads();
        if (tid == 0) {
            int run = 0;
            woff[0] = 0;
            #pragma unroll
            for (int wgi = 1; wgi <= 32; ++wgi) { run += woff[wgi]; woff[wgi] = run; }
        }
        __syncthreads();
        int pre = woff[tid >> 5] + (sv - v);
        if (f0) {
            int pos = g * (N_ - K_) + pre;
            g_permc[pos]      = base + e0;
            out_perm_com[pos] = (float)(base + e0);
        }
        if (f1) {
            int pos = g * (N_ - K_) + pre + f0;
            g_permc[pos]      = base + e1;
            out_perm_com[pos] = (float)(base + e1);
        }
    }

    // publish: all stores visible, then raise flag
    __threadfence();
    __syncthreads();
    if (tid == 0) atomicExch(&g_done[g], 1);
}

// ---------------- launch ----------------------------------------------------

extern "C" void kernel_launch(void* const* d_in, const int* in_sizes, int n_in,
                              void* d_out, int out_size) {
    const float* feature = (const float*)d_in[0];
    const float* W       = (const float*)d_in[1];
    const float* b       = (const float*)d_in[2];
    const int*   src     = (const int*)d_in[3];
    const int*   dst     = (const int*)d_in[4];

    float* out = (float*)d_out;
    float* out_dist     = out;                                  // BK_*D_
    float* out_com      = out + (size_t)BK_ * D_;               // BK_*D_
    float* out_full     = out + (size_t)2 * BK_ * D_;           // BN_*D_
    float* out_perm     = out + (size_t)2 * BK_ * D_ + (size_t)BN_ * D_;
    float* out_perm_com = out_perm + BK_;
    float* out_sm       = out_perm_com + BK_;

    init_kernel<<<(BN_ + 255) / 256, 256>>>();
    degdot_kernel<<<2 * NCTA_, 256>>>(src, feature, W);
    scatter_kernel<<<NCTA_, 256>>>(src, dst);
    finalize_kernel<<<(BN_ + 255) / 256, 256>>>(b);
    backend_kernel<<<B_ + FULL_B_ + PERM_B_, 1024>>>(
        feature, out_perm, out_perm_com, out_full, out_sm, out_dist, out_com);
}

// round 9
// speedup vs baseline: 1.0384x; 1.0384x over previous
#include <cuda_runtime.h>
#include <cuda_bf16.h>
#include <cstdint>

// Problem constants (fixed shapes)
static constexpr int B_   = 64;
static constexpr int N_   = 2048;
static constexpr int D_   = 128;
static constexpr int K_   = 1024;          // ceil(0.5 * N)
static constexpr int BN_  = B_ * N_;       // 131072 nodes
static constexpr int BK_  = B_ * K_;       // 65536 kept nodes
static constexpr int EPG_ = N_ * 32;       // 65536 edges per graph
static constexpr int NPC_ = 8;             // CTAs per graph (deg & scatter)
static constexpr int EPC_ = EPG_ / NPC_;   // 8192 edges per CTA
static constexpr int NCTA_ = B_ * NPC_;    // 512

// fixed-point encoding: per-edge add  llround((m+16)*2^40) + (1<<56)
//   low 56 bits : sum of (m+16)*2^40  (positive, < 2^53 total)
//   bits 56..63 : indeg count (< 256)
static constexpr unsigned long long TAG_  = 1ULL << 56;
static constexpr unsigned long long MASK_ = TAG_ - 1ULL;

static constexpr int FULL_B_ = BN_ / 32;   // 4096 full-emit blocks in sortemit

// ---------------- scratch (device globals; no allocation allowed) ----------
__device__ int                g_out[BN_];     // outdeg (global atomic merge)
__device__ unsigned long long g_spu2[BN_];    // fused sum+indeg (atomic merge)
__device__ float2             g_s[BN_];       // dot product (hi, lo)
__device__ float  g_score[BN_];
__device__ float  g_t[BN_];
__device__ int    g_perm[BK_];                // kept rows    (global ids)
__device__ int    g_permc[BK_];               // dropped rows (global ids)
__device__ float  g_sumexp;

// monotonic float->uint mapping (for sort keys)
__device__ __forceinline__ unsigned int ford(float f) {
    unsigned int u = __float_as_uint(f);
    return (u & 0x80000000u) ? ~u : (u | 0x80000000u);
}

// error-free addition: s + e == a + b exactly.
__device__ __forceinline__ void two_sum(float a, float b, float& s, float& e) {
    float s_ = a + b;
    float bb = s_ - a;
    e = (a - (s_ - bb)) + (b - bb);
    s = s_;
}

// ---------------- kernels ---------------------------------------------------

__global__ void init_kernel() {
    int i = blockIdx.x * blockDim.x + threadIdx.x;
    if (i < BN_) { g_out[i] = 0; g_spu2[i] = 0ULL; }
    if (i == 0)  g_sumexp = 0.0f;
}

// Grid-fused: blocks [0,512)    = src histogram -> global atomic merge;
//             blocks [512,1024) = compensated dot (DRAM bound, pipelined).
__global__ __launch_bounds__(256) void degdot_kernel(const int* __restrict__ src,
                                                     const float* __restrict__ feat,
                                                     const float* __restrict__ W) {
    const int tid = threadIdx.x;
    if (blockIdx.x < NCTA_) {
        // ---- deg path ----
        __shared__ int h[N_];
        const int c = blockIdx.x;
        const int g = c >> 3, sub = c & 7;
        for (int i = tid; i < N_; i += 256) h[i] = 0;
        __syncthreads();
        const int4* p = reinterpret_cast<const int4*>(src + g * EPG_ + sub * EPC_);
        #pragma unroll
        for (int it = 0; it < EPC_ / (256 * 4); ++it) {
            int4 v = p[tid + it * 256];
            atomicAdd(&h[v.x & (N_ - 1)], 1);
            atomicAdd(&h[v.y & (N_ - 1)], 1);
            atomicAdd(&h[v.z & (N_ - 1)], 1);
            atomicAdd(&h[v.w & (N_ - 1)], 1);
        }
        __syncthreads();
        for (int i = tid; i < N_; i += 256)
            atomicAdd(&g_out[g * N_ + i], h[i]);
    } else {
        // ---- dot path: 8 warps x 32 rows, software-pipelined loads ----
        const int c2   = blockIdx.x - NCTA_;          // 0..511
        const int wip  = tid >> 5;
        const int lane = tid & 31;
        const int row0 = c2 * 256 + wip * 32;
        const float4 wv = __ldg(reinterpret_cast<const float4*>(W) + lane);
        const float4* fp = reinterpret_cast<const float4*>(feat) + (size_t)row0 * 32 + lane;

        float4 f = __ldg(fp);
        #pragma unroll 4
        for (int i = 0; i < 32; ++i) {
            float4 fn;
            if (i < 31) fn = __ldg(fp + (size_t)(i + 1) * 32);   // prefetch next row
            float p0 = f.x * wv.x, e0 = fmaf(f.x, wv.x, -p0);
            float p1 = f.y * wv.y, e1 = fmaf(f.y, wv.y, -p1);
            float p2 = f.z * wv.z, e2 = fmaf(f.z, wv.z, -p2);
            float p3 = f.w * wv.w, e3 = fmaf(f.w, wv.w, -p3);
            float hi, lo, err;
            two_sum(p0, p1, hi, lo);
            two_sum(hi, p2, hi, err); lo += err;
            two_sum(hi, p3, hi, err); lo += err;
            lo += (e0 + e1) + (e2 + e3);
            #pragma unroll
            for (int o = 16; o > 0; o >>= 1) {
                float h2 = __shfl_xor_sync(0xFFFFFFFFu, hi, o);
                float l2 = __shfl_xor_sync(0xFFFFFFFFu, lo, o);
                two_sum(hi, h2, hi, err);
                lo += l2 + err;
            }
            if (lane == 0) g_s[row0 + i] = make_float2(hi, lo);
            f = fn;
        }
    }
}

// Scatter: build messages in-CTA (rsqrt table), stage in SMEM, one u64 SMEM
// atomic per edge, flush via global u64 atomicAdd (exact integer merge).
__global__ __launch_bounds__(256) void scatter_kernel(const int* __restrict__ src,
                                                      const int* __restrict__ dst) {
    __shared__ double rsqd[256];             // 2KB
    __shared__ unsigned long long acc[N_];   // 16KB
    __shared__ unsigned long long msg[N_];   // 16KB
    const int c = blockIdx.x;
    const int g = c >> 3, sub = c & 7;
    const int tid = threadIdx.x;
    const int gb = g * N_;

    rsqd[tid] = 1.0 / sqrt((double)(tid < 1 ? 1 : tid));
    for (int i = tid; i < N_; i += 256) acc[i] = 0ULL;
    __syncthreads();

    for (int i = tid; i < N_; i += 256) {
        int od = g_out[gb + i];
        od = od < 1 ? 1 : (od > 255 ? 255 : od);
        float2 s2 = g_s[gb + i];
        double s = (double)s2.x + (double)s2.y;
        double m = s * rsqd[od];
        msg[i] = (unsigned long long)llround((m + 16.0) * 0x1p40) + TAG_;
    }
    __syncthreads();

    const int4* ps = reinterpret_cast<const int4*>(src + g * EPG_ + sub * EPC_);
    const int4* pd = reinterpret_cast<const int4*>(dst + g * EPG_ + sub * EPC_);
    #pragma unroll
    for (int it = 0; it < EPC_ / (256 * 4); ++it) {
        int4 s4 = ps[tid + it * 256];
        int4 d4 = pd[tid + it * 256];
        atomicAdd(&acc[d4.x & (N_ - 1)], msg[s4.x & (N_ - 1)]);
        atomicAdd(&acc[d4.y & (N_ - 1)], msg[s4.y & (N_ - 1)]);
        atomicAdd(&acc[d4.z & (N_ - 1)], msg[s4.z & (N_ - 1)]);
        atomicAdd(&acc[d4.w & (N_ - 1)], msg[s4.w & (N_ - 1)]);
    }
    __syncthreads();
    for (int i = tid; i < N_; i += 256)
        atomicAdd(&g_spu2[gb + i], acc[i]);
}

// Decode merged u64; score = sum*rsqrt(indeg) + b; t = tanh; sumexp reduce.
// 4 nodes per thread, loads batched for MLP=4.
__global__ __launch_bounds__(256) void finalize_kernel(const float* __restrict__ b) {
    __shared__ double rsqd[256];
    __shared__ float sm[32];
    const int tid = threadIdx.x;
    rsqd[tid] = 1.0 / sqrt((double)(tid < 1 ? 1 : tid));
    __syncthreads();

    const int v0 = (blockIdx.x * blockDim.x + tid) * 4;
    const double bb = (double)__ldg(b);

    unsigned long long a0 = g_spu2[v0 + 0];
    unsigned long long a1 = g_spu2[v0 + 1];
    unsigned long long a2 = g_spu2[v0 + 2];
    unsigned long long a3 = g_spu2[v0 + 3];

    float e = 0.0f;
    float sc4[4];
    unsigned long long aa[4] = {a0, a1, a2, a3};
    #pragma unroll
    for (int q = 0; q < 4; ++q) {
        unsigned long long a = aa[q];
        int id = (int)(a >> 56);
        double sum = (double)(a & MASK_) * 0x1p-40 - 16.0 * (double)id;
        double sd = sum * rsqd[id < 1 ? 1 : id] + bb;
        float sc = (float)sd;
        sc4[q] = sc;
        e += __expf(sc);
    }
    // batched stores
    reinterpret_cast<float4*>(g_score)[v0 >> 2] =
        make_float4(sc4[0], sc4[1], sc4[2], sc4[3]);
    reinterpret_cast<float4*>(g_t)[v0 >> 2] =
        make_float4(tanhf(sc4[0]), tanhf(sc4[1]), tanhf(sc4[2]), tanhf(sc4[3]));

    #pragma unroll
    for (int o = 16; o > 0; o >>= 1) e += __shfl_xor_sync(0xFFFFFFFFu, e, o);
    int lane = tid & 31, wid = tid >> 5;
    if (lane == 0) sm[wid] = e;
    __syncthreads();
    if (wid == 0) {
        e = (lane < (blockDim.x >> 5)) ? sm[lane] : 0.0f;
        #pragma unroll
        for (int o = 16; o > 0; o >>= 1) e += __shfl_xor_sync(0xFFFFFFFFu, e, o);
        if (lane == 0) atomicAdd(&g_sumexp, e);
    }
}

// register-phase bitonic compare-exchange (j <= 16, within warp)
__device__ __forceinline__ void reg_ex(unsigned long long& key, int i, int j, int k) {
    unsigned long long p = __shfl_xor_sync(0xFFFFFFFFu, key, j);
    bool up  = ((i & k) == 0);
    bool low = ((i & j) == 0);
    unsigned long long mn = key < p ? key : p;
    unsigned long long mx = key < p ? p : key;
    key = (low == up) ? mn : mx;
}

// Grid-fused: blocks [0,64) = per-graph sort -> perms;
//             blocks [64, 64+4096) = emit feature_full + score_sm.
__global__ __launch_bounds__(1024) void sortemit_kernel(const float* __restrict__ feat,
                                                        float* __restrict__ out_perm,
                                                        float* __restrict__ out_perm_com,
                                                        float* __restrict__ out_full,
                                                        float* __restrict__ out_sm) {
    __shared__ unsigned long long keys[N_];
    __shared__ int flags[N_];
    __shared__ int woff[33];

    const int tid = threadIdx.x;

    if (blockIdx.x >= B_) {
        // ---- full-emit path: one warp per node row ----
        int w    = (blockIdx.x - B_) * 32 + (tid >> 5);
        int lane = tid & 31;
        float t = g_t[w];
        float4 f = __ldg(reinterpret_cast<const float4*>(feat) + (size_t)w * 32 + lane);
        f.x *= t; f.y *= t; f.z *= t; f.w *= t;
        reinterpret_cast<float4*>(out_full + (size_t)w * D_)[lane] = f;
        if (lane == 0) out_sm[w] = __expf(g_score[w]) / g_sumexp;
        return;
    }

    // ---- sort path ----
    const int g    = blockIdx.x;
    const int base = g * N_;
    const int i0 = tid, i1 = tid + 1024;

    unsigned long long k0, k1;
    {
        unsigned int a = ~ford(g_score[base + i0]);
        unsigned int b = ~ford(g_score[base + i1]);
        k0 = ((unsigned long long)a << 32) | (unsigned int)i0;
        k1 = ((unsigned long long)b << 32) | (unsigned int)i1;
    }

    // k = 2..32 entirely in registers
    #pragma unroll
    for (int k = 2; k <= 32; k <<= 1)
        for (int j = k >> 1; j >= 1; j >>= 1) { reg_ex(k0, i0, j, k); reg_ex(k1, i1, j, k); }

    // k = 64..2048: SMEM passes for j>=32, register passes for j<=16
    for (int k = 64; k <= N_; k <<= 1) {
        keys[i0] = k0; keys[i1] = k1;
        __syncthreads();
        for (int j = k >> 1; j >= 32; j >>= 1) {
            #pragma unroll
            for (int r = 0; r < 2; r++) {
                int i = tid + r * 1024;
                int ixj = i ^ j;
                if (ixj > i) {
                    unsigned long long a = keys[i], c = keys[ixj];
                    bool up = ((i & k) == 0);
                    if ((a > c) == up) { keys[i] = c; keys[ixj] = a; }
                }
            }
            __syncthreads();
        }
        k0 = keys[i0]; k1 = keys[i1];
        #pragma unroll
        for (int j = 16; j >= 1; j >>= 1) { reg_ex(k0, i0, j, k); reg_ex(k1, i1, j, k); }
    }
    keys[i0] = k0; keys[i1] = k1;
    __syncthreads();

    // flags: 1 = unselected
    flags[i0] = 1; flags[i1] = 1;
    __syncthreads();

    // top K_ = first 1024 sorted entries
    {
        int local = (int)(unsigned int)(keys[tid] & 0xFFFFFFFFull);
        flags[local] = 0;
        int gid = base + local;
        g_perm[g * K_ + tid]   = gid;
        out_perm[g * K_ + tid] = (float)gid;
    }
    __syncthreads();

    // warp-shfl scan over contiguous pairs
    {
        int e0 = 2 * tid, e1 = 2 * tid + 1;
        int f0 = flags[e0], f1 = flags[e1];
        int v = f0 + f1;
        int sv = v;
        #pragma unroll
        for (int o = 1; o < 32; o <<= 1) {
            int n = __shfl_up_sync(0xFFFFFFFFu, sv, o);
            if ((tid & 31) >= o) sv += n;
        }
        if ((tid & 31) == 31) woff[(tid >> 5) + 1] = sv;
        __syncthreads();
        if (tid == 0) {
            int run = 0;
            woff[0] = 0;
            #pragma unroll
            for (int wgi = 1; wgi <= 32; ++wgi) { run += woff[wgi]; woff[wgi] = run; }
        }
        __syncthreads();
        int pre = woff[tid >> 5] + (sv - v);
        if (f0) {
            int pos = g * (N_ - K_) + pre;
            g_permc[pos]      = base + e0;
            out_perm_com[pos] = (float)(base + e0);
        }
        if (f1) {
            int pos = g * (N_ - K_) + pre + f0;
            g_permc[pos]      = base + e1;
            out_perm_com[pos] = (float)(base + e1);
        }
    }
}

// dist/com = row copies from out_full (already scaled; L2-warm).
// One warp per output row.
__global__ __launch_bounds__(1024) void emitperm_kernel(const float* __restrict__ out_full,
                                                        float* __restrict__ out_dist,
                                                        float* __restrict__ out_com) {
    int gtid = blockIdx.x * blockDim.x + threadIdx.x;
    int r    = gtid >> 5;
    int lane = gtid & 31;
    int p;
    float* o;
    if (r < BK_) {
        p = g_perm[r];
        o = out_dist + (size_t)r * D_;
    } else {
        int rc = r - BK_;
        p = g_permc[rc];
        o = out_com + (size_t)rc * D_;
    }
    float4 f = __ldg(reinterpret_cast<const float4*>(out_full) + (size_t)p * 32 + lane);
    reinterpret_cast<float4*>(o)[lane] = f;
}

// ---------------- launch ----------------------------------------------------

extern "C" void kernel_launch(void* const* d_in, const int* in_sizes, int n_in,
                              void* d_out, int out_size) {
    const float* feature = (const float*)d_in[0];
    const float* W       = (const float*)d_in[1];
    const float* b       = (const float*)d_in[2];
    const int*   src     = (const int*)d_in[3];
    const int*   dst     = (const int*)d_in[4];

    float* out = (float*)d_out;
    float* out_dist     = out;                                  // BK_*D_
    float* out_com      = out + (size_t)BK_ * D_;               // BK_*D_
    float* out_full     = out + (size_t)2 * BK_ * D_;           // BN_*D_
    float* out_perm     = out + (size_t)2 * BK_ * D_ + (size_t)BN_ * D_;
    float* out_perm_com = out_perm + BK_;
    float* out_sm       = out_perm_com + BK_;

    init_kernel<<<(BN_ + 255) / 256, 256>>>();
    degdot_kernel<<<2 * NCTA_, 256>>>(src, feature, W);
    scatter_kernel<<<NCTA_, 256>>>(src, dst);
    finalize_kernel<<<BN_ / (256 * 4), 256>>>(b);
    sortemit_kernel<<<B_ + FULL_B_, 1024>>>(feature, out_perm, out_perm_com,
                                            out_full, out_sm);
    emitperm_kernel<<<(2 * BK_) / 32, 1024>>>(out_full, out_dist, out_com);
}

// round 10
// speedup vs baseline: 1.1178x; 1.0765x over previous
#include <cuda_runtime.h>
#include <cuda_bf16.h>
#include <cstdint>

// Problem constants (fixed shapes)
static constexpr int B_   = 64;
static constexpr int N_   = 2048;
static constexpr int D_   = 128;
static constexpr int K_   = 1024;          // ceil(0.5 * N)
static constexpr int BN_  = B_ * N_;       // 131072 nodes
static constexpr int BK_  = B_ * K_;       // 65536 kept nodes
static constexpr int EPG_ = N_ * 32;       // 65536 edges per graph
static constexpr int NPC_ = 8;             // CTAs per graph (deg & scatter)
static constexpr int EPC_ = EPG_ / NPC_;   // 8192 edges per CTA
static constexpr int NCTA_ = B_ * NPC_;    // 512

// fixed-point encoding: per-edge add  llround((m+16)*2^40) + (1<<56)
//   low 56 bits : sum of (m+16)*2^40  (positive, < 2^53 total)
//   bits 56..63 : indeg count (< 256)
static constexpr unsigned long long TAG_  = 1ULL << 56;
static constexpr unsigned long long MASK_ = TAG_ - 1ULL;

static constexpr int FULL_B_ = BN_ / 128;      // 1024 full-emit blocks (4 rows/warp)
static constexpr int PERM_B_ = 2 * BK_ / 128;  // 1024 perm-emit blocks (4 rows/warp)

// ---------------- scratch (device globals; no allocation allowed) ----------
__device__ int                g_out[BN_];     // outdeg (global atomic merge)
__device__ unsigned long long g_spu2[BN_];    // fused sum+indeg (atomic merge)
__device__ float2             g_s[BN_];       // dot product (hi, lo)
__device__ float  g_score[BN_];
__device__ float  g_t[BN_];
__device__ int    g_perm[BK_];                // kept rows    (global ids)
__device__ int    g_permc[BK_];               // dropped rows (global ids)
__device__ float  g_sumexp;

// monotonic float->uint mapping (for sort keys)
__device__ __forceinline__ unsigned int ford(float f) {
    unsigned int u = __float_as_uint(f);
    return (u & 0x80000000u) ? ~u : (u | 0x80000000u);
}

// error-free addition: s + e == a + b exactly.
__device__ __forceinline__ void two_sum(float a, float b, float& s, float& e) {
    float s_ = a + b;
    float bb = s_ - a;
    e = (a - (s_ - bb)) + (b - bb);
    s = s_;
}

// ---------------- kernels ---------------------------------------------------

__global__ void init_kernel() {
    int i = blockIdx.x * blockDim.x + threadIdx.x;
    if (i < BN_) { g_out[i] = 0; g_spu2[i] = 0ULL; }
    if (i == 0)  g_sumexp = 0.0f;
}

// Grid-fused: blocks [0,512)    = src histogram -> global atomic merge;
//             blocks [512,1024) = compensated dot (DRAM bound, depth-4 prefetch).
__global__ __launch_bounds__(256) void degdot_kernel(const int* __restrict__ src,
                                                     const float* __restrict__ feat,
                                                     const float* __restrict__ W) {
    const int tid = threadIdx.x;
    if (blockIdx.x < NCTA_) {
        // ---- deg path ----
        __shared__ int h[N_];
        const int c = blockIdx.x;
        const int g = c >> 3, sub = c & 7;
        for (int i = tid; i < N_; i += 256) h[i] = 0;
        __syncthreads();
        const int4* p = reinterpret_cast<const int4*>(src + g * EPG_ + sub * EPC_);
        #pragma unroll
        for (int it = 0; it < EPC_ / (256 * 4); ++it) {
            int4 v = p[tid + it * 256];
            atomicAdd(&h[v.x & (N_ - 1)], 1);
            atomicAdd(&h[v.y & (N_ - 1)], 1);
            atomicAdd(&h[v.z & (N_ - 1)], 1);
            atomicAdd(&h[v.w & (N_ - 1)], 1);
        }
        __syncthreads();
        for (int i = tid; i < N_; i += 256)
            atomicAdd(&g_out[g * N_ + i], h[i]);
    } else {
        // ---- dot path: 8 warps x 32 rows, prefetch ring depth 4 ----
        const int c2   = blockIdx.x - NCTA_;          // 0..511
        const int wip  = tid >> 5;
        const int lane = tid & 31;
        const int row0 = c2 * 256 + wip * 32;
        const float4 wv = __ldg(reinterpret_cast<const float4*>(W) + lane);
        const float4* fp = reinterpret_cast<const float4*>(feat) + (size_t)row0 * 32 + lane;

        float4 buf[4];
        #pragma unroll
        for (int q = 0; q < 4; ++q) buf[q] = __ldg(fp + (size_t)q * 32);

        #pragma unroll
        for (int i = 0; i < 32; ++i) {
            float4 f = buf[i & 3];
            if (i + 4 < 32) buf[i & 3] = __ldg(fp + (size_t)(i + 4) * 32);
            float p0 = f.x * wv.x, e0 = fmaf(f.x, wv.x, -p0);
            float p1 = f.y * wv.y, e1 = fmaf(f.y, wv.y, -p1);
            float p2 = f.z * wv.z, e2 = fmaf(f.z, wv.z, -p2);
            float p3 = f.w * wv.w, e3 = fmaf(f.w, wv.w, -p3);
            float hi, lo, err;
            two_sum(p0, p1, hi, lo);
            two_sum(hi, p2, hi, err); lo += err;
            two_sum(hi, p3, hi, err); lo += err;
            lo += (e0 + e1) + (e2 + e3);
            #pragma unroll
            for (int o = 16; o > 0; o >>= 1) {
                float h2 = __shfl_xor_sync(0xFFFFFFFFu, hi, o);
                float l2 = __shfl_xor_sync(0xFFFFFFFFu, lo, o);
                two_sum(hi, h2, hi, err);
                lo += l2 + err;
            }
            if (lane == 0) g_s[row0 + i] = make_float2(hi, lo);
        }
    }
}

// Scatter: build messages in-CTA (rsqrt table), stage in SMEM, one u64 SMEM
// atomic per edge, flush via global u64 atomicAdd (exact integer merge).
__global__ __launch_bounds__(256) void scatter_kernel(const int* __restrict__ src,
                                                      const int* __restrict__ dst) {
    __shared__ double rsqd[256];             // 2KB
    __shared__ unsigned long long acc[N_];   // 16KB
    __shared__ unsigned long long msg[N_];   // 16KB
    const int c = blockIdx.x;
    const int g = c >> 3, sub = c & 7;
    const int tid = threadIdx.x;
    const int gb = g * N_;

    rsqd[tid] = 1.0 / sqrt((double)(tid < 1 ? 1 : tid));
    for (int i = tid; i < N_; i += 256) acc[i] = 0ULL;
    __syncthreads();

    for (int i = tid; i < N_; i += 256) {
        int od = g_out[gb + i];
        od = od < 1 ? 1 : (od > 255 ? 255 : od);
        float2 s2 = g_s[gb + i];
        double s = (double)s2.x + (double)s2.y;
        double m = s * rsqd[od];
        msg[i] = (unsigned long long)llround((m + 16.0) * 0x1p40) + TAG_;
    }
    __syncthreads();

    const int4* ps = reinterpret_cast<const int4*>(src + g * EPG_ + sub * EPC_);
    const int4* pd = reinterpret_cast<const int4*>(dst + g * EPG_ + sub * EPC_);
    #pragma unroll
    for (int it = 0; it < EPC_ / (256 * 4); ++it) {
        int4 s4 = ps[tid + it * 256];
        int4 d4 = pd[tid + it * 256];
        atomicAdd(&acc[d4.x & (N_ - 1)], msg[s4.x & (N_ - 1)]);
        atomicAdd(&acc[d4.y & (N_ - 1)], msg[s4.y & (N_ - 1)]);
        atomicAdd(&acc[d4.z & (N_ - 1)], msg[s4.z & (N_ - 1)]);
        atomicAdd(&acc[d4.w & (N_ - 1)], msg[s4.w & (N_ - 1)]);
    }
    __syncthreads();
    for (int i = tid; i < N_; i += 256)
        atomicAdd(&g_spu2[gb + i], acc[i]);
}

// Decode merged u64; score = sum*rsqrt(indeg) + b; t = tanh; sumexp reduce.
// 2 nodes per thread, grid 256 (>=1 CTA/SM), MLP=2.
__global__ __launch_bounds__(256) void finalize_kernel(const float* __restrict__ b) {
    __shared__ double rsqd[256];
    __shared__ float sm[32];
    const int tid = threadIdx.x;
    rsqd[tid] = 1.0 / sqrt((double)(tid < 1 ? 1 : tid));
    __syncthreads();

    const int v0 = (blockIdx.x * blockDim.x + tid) * 2;
    const double bb = (double)__ldg(b);

    unsigned long long a0 = g_spu2[v0 + 0];
    unsigned long long a1 = g_spu2[v0 + 1];

    float e = 0.0f;
    float sc2[2];
    unsigned long long aa[2] = {a0, a1};
    #pragma unroll
    for (int q = 0; q < 2; ++q) {
        unsigned long long a = aa[q];
        int id = (int)(a >> 56);
        double sum = (double)(a & MASK_) * 0x1p-40 - 16.0 * (double)id;
        double sd = sum * rsqd[id < 1 ? 1 : id] + bb;
        float sc = (float)sd;
        sc2[q] = sc;
        e += __expf(sc);
    }
    reinterpret_cast<float2*>(g_score)[v0 >> 1] = make_float2(sc2[0], sc2[1]);
    reinterpret_cast<float2*>(g_t)[v0 >> 1] = make_float2(tanhf(sc2[0]), tanhf(sc2[1]));

    #pragma unroll
    for (int o = 16; o > 0; o >>= 1) e += __shfl_xor_sync(0xFFFFFFFFu, e, o);
    int lane = tid & 31, wid = tid >> 5;
    if (lane == 0) sm[wid] = e;
    __syncthreads();
    if (wid == 0) {
        e = (lane < (blockDim.x >> 5)) ? sm[lane] : 0.0f;
        #pragma unroll
        for (int o = 16; o > 0; o >>= 1) e += __shfl_xor_sync(0xFFFFFFFFu, e, o);
        if (lane == 0) atomicAdd(&g_sumexp, e);
    }
}

// register-phase bitonic compare-exchange (j <= 16, within warp)
__device__ __forceinline__ void reg_ex(unsigned long long& key, int i, int j, int k) {
    unsigned long long p = __shfl_xor_sync(0xFFFFFFFFu, key, j);
    bool up  = ((i & k) == 0);
    bool low = ((i & j) == 0);
    unsigned long long mn = key < p ? key : p;
    unsigned long long mx = key < p ? p : key;
    key = (low == up) ? mn : mx;
}

// Grid-fused: blocks [0,64) = per-graph sort -> perms;
//             blocks [64, 64+1024) = emit feature_full + score_sm (4 rows/warp).
__global__ __launch_bounds__(1024) void sortemit_kernel(const float* __restrict__ feat,
                                                        float* __restrict__ out_perm,
                                                        float* __restrict__ out_perm_com,
                                                        float* __restrict__ out_full,
                                                        float* __restrict__ out_sm) {
    __shared__ unsigned long long keys[N_];
    __shared__ int flags[N_];
    __shared__ int woff[33];

    const int tid = threadIdx.x;

    if (blockIdx.x >= B_) {
        // ---- full-emit: 4 rows per warp, loads batched (MLP 4) ----
        const int warp = tid >> 5, lane = tid & 31;
        const int r0 = (blockIdx.x - B_) * 128 + warp;   // rows r0 + {0,32,64,96}
        float4 f[4]; float t[4];
        #pragma unroll
        for (int q = 0; q < 4; ++q) {
            int w = r0 + q * 32;
            f[q] = __ldg(reinterpret_cast<const float4*>(feat) + (size_t)w * 32 + lane);
            t[q] = g_t[w];
        }
        #pragma unroll
        for (int q = 0; q < 4; ++q) {
            int w = r0 + q * 32;
            float4 v = f[q];
            v.x *= t[q]; v.y *= t[q]; v.z *= t[q]; v.w *= t[q];
            reinterpret_cast<float4*>(out_full + (size_t)w * D_)[lane] = v;
            if (lane == 0) out_sm[w] = __expf(g_score[w]) / g_sumexp;
        }
        return;
    }

    // ---- sort path ----
    const int g    = blockIdx.x;
    const int base = g * N_;
    const int i0 = tid, i1 = tid + 1024;

    unsigned long long k0, k1;
    {
        unsigned int a = ~ford(g_score[base + i0]);
        unsigned int b = ~ford(g_score[base + i1]);
        k0 = ((unsigned long long)a << 32) | (unsigned int)i0;
        k1 = ((unsigned long long)b << 32) | (unsigned int)i1;
    }

    // k = 2..32 entirely in registers
    #pragma unroll
    for (int k = 2; k <= 32; k <<= 1)
        for (int j = k >> 1; j >= 1; j >>= 1) { reg_ex(k0, i0, j, k); reg_ex(k1, i1, j, k); }

    // k = 64..2048: SMEM passes for j>=32, register passes for j<=16
    for (int k = 64; k <= N_; k <<= 1) {
        keys[i0] = k0; keys[i1] = k1;
        __syncthreads();
        for (int j = k >> 1; j >= 32; j >>= 1) {
            #pragma unroll
            for (int r = 0; r < 2; r++) {
                int i = tid + r * 1024;
                int ixj = i ^ j;
                if (ixj > i) {
                    unsigned long long a = keys[i], c = keys[ixj];
                    bool up = ((i & k) == 0);
                    if ((a > c) == up) { keys[i] = c; keys[ixj] = a; }
                }
            }
            __syncthreads();
        }
        k0 = keys[i0]; k1 = keys[i1];
        #pragma unroll
        for (int j = 16; j >= 1; j >>= 1) { reg_ex(k0, i0, j, k); reg_ex(k1, i1, j, k); }
    }
    keys[i0] = k0; keys[i1] = k1;
    __syncthreads();

    // flags: 1 = unselected
    flags[i0] = 1; flags[i1] = 1;
    __syncthreads();

    // top K_ = first 1024 sorted entries
    {
        int local = (int)(unsigned int)(keys[tid] & 0xFFFFFFFFull);
        flags[local] = 0;
        int gid = base + local;
        g_perm[g * K_ + tid]   = gid;
        out_perm[g * K_ + tid] = (float)gid;
    }
    __syncthreads();

    // warp-shfl scan over contiguous pairs
    {
        int e0 = 2 * tid, e1 = 2 * tid + 1;
        int f0 = flags[e0], f1 = flags[e1];
        int v = f0 + f1;
        int sv = v;
        #pragma unroll
        for (int o = 1; o < 32; o <<= 1) {
            int n = __shfl_up_sync(0xFFFFFFFFu, sv, o);
            if ((tid & 31) >= o) sv += n;
        }
        if ((tid & 31) == 31) woff[(tid >> 5) + 1] = sv;
        __syncthreads();
        if (tid == 0) {
            int run = 0;
            woff[0] = 0;
            #pragma unroll
            for (int wgi = 1; wgi <= 32; ++wgi) { run += woff[wgi]; woff[wgi] = run; }
        }
        __syncthreads();
        int pre = woff[tid >> 5] + (sv - v);
        if (f0) {
            int pos = g * (N_ - K_) + pre;
            g_permc[pos]      = base + e0;
            out_perm_com[pos] = (float)(base + e0);
        }
        if (f1) {
            int pos = g * (N_ - K_) + pre + f0;
            g_permc[pos]      = base + e1;
            out_perm_com[pos] = (float)(base + e1);
        }
    }
}

// dist/com = row copies from out_full (L2-warm). 4 rows per warp (MLP 4).
__global__ __launch_bounds__(1024) void emitperm_kernel(const float* __restrict__ out_full,
                                                        float* __restrict__ out_dist,
                                                        float* __restrict__ out_com) {
    const int warp = threadIdx.x >> 5, lane = threadIdx.x & 31;
    const int r0 = blockIdx.x * 128 + warp;         // rows r0 + {0,32,64,96}

    float4 f[4]; float* o[4];
    #pragma unroll
    for (int q = 0; q < 4; ++q) {
        int r = r0 + q * 32;
        int p;
        if (r < BK_) {
            p = g_perm[r];
            o[q] = out_dist + (size_t)r * D_;
        } else {
            int rc = r - BK_;
            p = g_permc[rc];
            o[q] = out_com + (size_t)rc * D_;
        }
        f[q] = __ldg(reinterpret_cast<const float4*>(out_full) + (size_t)p * 32 + lane);
    }
    #pragma unroll
    for (int q = 0; q < 4; ++q)
        reinterpret_cast<float4*>(o[q])[lane] = f[q];
}

// ---------------- launch ----------------------------------------------------

extern "C" void kernel_launch(void* const* d_in, const int* in_sizes, int n_in,
                              void* d_out, int out_size) {
    const float* feature = (const float*)d_in[0];
    const float* W       = (const float*)d_in[1];
    const float* b       = (const float*)d_in[2];
    const int*   src     = (const int*)d_in[3];
    const int*   dst     = (const int*)d_in[4];

    float* out = (float*)d_out;
    float* out_dist     = out;                                  // BK_*D_
    float* out_com      = out + (size_t)BK_ * D_;               // BK_*D_
    float* out_full     = out + (size_t)2 * BK_ * D_;           // BN_*D_
    float* out_perm     = out + (size_t)2 * BK_ * D_ + (size_t)BN_ * D_;
    float* out_perm_com = out_perm + BK_;
    float* out_sm       = out_perm_com + BK_;

    init_kernel<<<(BN_ + 255) / 256, 256>>>();
    degdot_kernel<<<2 * NCTA_, 256>>>(src, feature, W);
    scatter_kernel<<<NCTA_, 256>>>(src, dst);
    finalize_kernel<<<BN_ / (256 * 2), 256>>>(b);
    sortemit_kernel<<<B_ + FULL_B_, 1024>>>(feature, out_perm, out_perm_com,
                                            out_full, out_sm);
    emitperm_kernel<<<PERM_B_, 1024>>>(out_full, out_dist, out_com);
}

// round 11
// speedup vs baseline: 1.2489x; 1.1173x over previous
#include <cuda_runtime.h>
#include <cuda_bf16.h>
#include <cstdint>

// Problem constants (fixed shapes)
static constexpr int B_   = 64;
static constexpr int N_   = 2048;
static constexpr int D_   = 128;
static constexpr int K_   = 1024;          // ceil(0.5 * N)
static constexpr int BN_  = B_ * N_;       // 131072 nodes
static constexpr int BK_  = B_ * K_;       // 65536 kept nodes
static constexpr int EPG_ = N_ * 32;       // 65536 edges per graph
static constexpr int NPC_ = 8;             // CTAs per graph (deg & scatter)
static constexpr int EPC_ = EPG_ / NPC_;   // 8192 edges per CTA
static constexpr int NCTA_ = B_ * NPC_;    // 512

// fixed-point encoding: per-edge add  llround((m+16)*2^40) + (1<<56)
//   low 56 bits : sum of (m+16)*2^40  (positive, < 2^53 total)
//   bits 56..63 : indeg count (< 256)
static constexpr unsigned long long TAG_  = 1ULL << 56;
static constexpr unsigned long long MASK_ = TAG_ - 1ULL;

static constexpr int FULL_B_ = BN_ / 128;      // 1024 full-emit blocks (4 rows/warp)
static constexpr int PERM_B_ = 2 * BK_ / 128;  // 1024 perm-emit blocks (4 rows/warp)

// ---------------- scratch (device globals; no allocation allowed) ----------
__device__ int                g_out[BN_];     // outdeg (global atomic merge)
__device__ unsigned long long g_spu2[BN_];    // fused sum+indeg (atomic merge)
__device__ float2             g_s[BN_];       // dot product (hi, lo)
__device__ double g_rsqd[256];                // 1/sqrt(max(i,1)) table
__device__ int    g_perm[BK_];                // kept rows    (global ids)
__device__ int    g_permc[BK_];               // dropped rows (global ids)
__device__ float  g_sumexp;

// monotonic float->uint mapping (for sort keys)
__device__ __forceinline__ unsigned int ford(float f) {
    unsigned int u = __float_as_uint(f);
    return (u & 0x80000000u) ? ~u : (u | 0x80000000u);
}

// error-free addition: s + e == a + b exactly.
__device__ __forceinline__ void two_sum(float a, float b, float& s, float& e) {
    float s_ = a + b;
    float bb = s_ - a;
    e = (a - (s_ - bb)) + (b - bb);
    s = s_;
}

// decode merged u64 -> fp32 score (deterministic; same ops at every call site)
__device__ __forceinline__ float decode_score(unsigned long long a, double bb,
                                              const double* rsq) {
    int id = (int)(a >> 56);
    double sum = (double)(a & MASK_) * 0x1p-40 - 16.0 * (double)id;
    return (float)(sum * rsq[id < 1 ? 1 : id] + bb);
}

// ---------------- kernels ---------------------------------------------------

__global__ void init_kernel() {
    int i = blockIdx.x * blockDim.x + threadIdx.x;
    if (i < BN_) { g_out[i] = 0; g_spu2[i] = 0ULL; }
    if (i < 256) g_rsqd[i] = 1.0 / sqrt((double)(i < 1 ? 1 : i));
    if (i == 0)  g_sumexp = 0.0f;
}

// Grid-fused: blocks [0,512)    = src histogram -> global atomic merge;
//             blocks [512,1024) = compensated dot (DRAM bound, depth-4 prefetch).
__global__ __launch_bounds__(256) void degdot_kernel(const int* __restrict__ src,
                                                     const float* __restrict__ feat,
                                                     const float* __restrict__ W) {
    const int tid = threadIdx.x;
    if (blockIdx.x < NCTA_) {
        // ---- deg path ----
        __shared__ int h[N_];
        const int c = blockIdx.x;
        const int g = c >> 3, sub = c & 7;
        for (int i = tid; i < N_; i += 256) h[i] = 0;
        __syncthreads();
        const int4* p = reinterpret_cast<const int4*>(src + g * EPG_ + sub * EPC_);
        #pragma unroll
        for (int it = 0; it < EPC_ / (256 * 4); ++it) {
            int4 v = p[tid + it * 256];
            atomicAdd(&h[v.x & (N_ - 1)], 1);
            atomicAdd(&h[v.y & (N_ - 1)], 1);
            atomicAdd(&h[v.z & (N_ - 1)], 1);
            atomicAdd(&h[v.w & (N_ - 1)], 1);
        }
        __syncthreads();
        for (int i = tid; i < N_; i += 256)
            atomicAdd(&g_out[g * N_ + i], h[i]);
    } else {
        // ---- dot path: 8 warps x 32 rows, prefetch ring depth 4 ----
        const int c2   = blockIdx.x - NCTA_;          // 0..511
        const int wip  = tid >> 5;
        const int lane = tid & 31;
        const int row0 = c2 * 256 + wip * 32;
        const float4 wv = __ldg(reinterpret_cast<const float4*>(W) + lane);
        const float4* fp = reinterpret_cast<const float4*>(feat) + (size_t)row0 * 32 + lane;

        float4 buf[4];
        #pragma unroll
        for (int q = 0; q < 4; ++q) buf[q] = __ldg(fp + (size_t)q * 32);

        #pragma unroll
        for (int i = 0; i < 32; ++i) {
            float4 f = buf[i & 3];
            if (i + 4 < 32) buf[i & 3] = __ldg(fp + (size_t)(i + 4) * 32);
            float p0 = f.x * wv.x, e0 = fmaf(f.x, wv.x, -p0);
            float p1 = f.y * wv.y, e1 = fmaf(f.y, wv.y, -p1);
            float p2 = f.z * wv.z, e2 = fmaf(f.z, wv.z, -p2);
            float p3 = f.w * wv.w, e3 = fmaf(f.w, wv.w, -p3);
            float hi, lo, err;
            two_sum(p0, p1, hi, lo);
            two_sum(hi, p2, hi, err); lo += err;
            two_sum(hi, p3, hi, err); lo += err;
            lo += (e0 + e1) + (e2 + e3);
            #pragma unroll
            for (int o = 16; o > 0; o >>= 1) {
                float h2 = __shfl_xor_sync(0xFFFFFFFFu, hi, o);
                float l2 = __shfl_xor_sync(0xFFFFFFFFu, lo, o);
                two_sum(hi, h2, hi, err);
                lo += l2 + err;
            }
            if (lane == 0) g_s[row0 + i] = make_float2(hi, lo);
        }
    }
}

// Scatter: build messages in-CTA (rsqrt table from global), stage in SMEM,
// one u64 SMEM atomic per edge, flush via global u64 atomicAdd (exact merge).
__global__ __launch_bounds__(256) void scatter_kernel(const int* __restrict__ src,
                                                      const int* __restrict__ dst) {
    __shared__ double rsqd[256];             // 2KB
    __shared__ unsigned long long acc[N_];   // 16KB
    __shared__ unsigned long long msg[N_];   // 16KB
    const int c = blockIdx.x;
    const int g = c >> 3, sub = c & 7;
    const int tid = threadIdx.x;
    const int gb = g * N_;

    rsqd[tid] = g_rsqd[tid];
    for (int i = tid; i < N_; i += 256) acc[i] = 0ULL;
    __syncthreads();

    for (int i = tid; i < N_; i += 256) {
        int od = g_out[gb + i];
        od = od < 1 ? 1 : (od > 255 ? 255 : od);
        float2 s2 = g_s[gb + i];
        double s = (double)s2.x + (double)s2.y;
        double m = s * rsqd[od];
        msg[i] = (unsigned long long)llround((m + 16.0) * 0x1p40) + TAG_;
    }
    __syncthreads();

    const int4* ps = reinterpret_cast<const int4*>(src + g * EPG_ + sub * EPC_);
    const int4* pd = reinterpret_cast<const int4*>(dst + g * EPG_ + sub * EPC_);
    #pragma unroll
    for (int it = 0; it < EPC_ / (256 * 4); ++it) {
        int4 s4 = ps[tid + it * 256];
        int4 d4 = pd[tid + it * 256];
        atomicAdd(&acc[d4.x & (N_ - 1)], msg[s4.x & (N_ - 1)]);
        atomicAdd(&acc[d4.y & (N_ - 1)], msg[s4.y & (N_ - 1)]);
        atomicAdd(&acc[d4.z & (N_ - 1)], msg[s4.z & (N_ - 1)]);
        atomicAdd(&acc[d4.w & (N_ - 1)], msg[s4.w & (N_ - 1)]);
    }
    __syncthreads();
    for (int i = tid; i < N_; i += 256)
        atomicAdd(&g_spu2[gb + i], acc[i]);
}

// register-phase bitonic compare-exchange (j <= 16, within warp)
__device__ __forceinline__ void reg_ex(unsigned long long& key, int i, int j, int k) {
    unsigned long long p = __shfl_xor_sync(0xFFFFFFFFu, key, j);
    bool up  = ((i & k) == 0);
    bool low = ((i & j) == 0);
    unsigned long long mn = key < p ? key : p;
    unsigned long long mx = key < p ? p : key;
    key = (low == up) ? mn : mx;
}

// Grid-fused backend, decodes u64 state directly (no finalize kernel):
//   blocks [0,64)        = per-graph sort -> perms;
//   blocks [64, 64+1024) = emit feature_full + exp(score) into out_sm
//                          (+ block-level sumexp atomicAdd).
__global__ __launch_bounds__(1024) void sortemit_kernel(const float* __restrict__ feat,
                                                        const float* __restrict__ b,
                                                        float* __restrict__ out_perm,
                                                        float* __restrict__ out_perm_com,
                                                        float* __restrict__ out_full,
                                                        float* __restrict__ out_sm) {
    __shared__ unsigned long long keys[N_];
    __shared__ int flags[N_];
    __shared__ int woff[33];
    __shared__ double rsqd_s[256];
    __shared__ float sm[32];

    const int tid = threadIdx.x;
    const double bb = (double)__ldg(b);

    if (blockIdx.x >= B_) {
        // ---- full-emit: 4 rows per warp; decode u64 in-register ----
        const int warp = tid >> 5, lane = tid & 31;
        const int r0 = (blockIdx.x - B_) * 128 + warp;   // rows r0 + {0,32,64,96}

        // lanes 0..3 decode one row each
        float tdec = 0.0f, edec = 0.0f;
        if (lane < 4) {
            unsigned long long a = g_spu2[r0 + lane * 32];
            float sc = decode_score(a, bb, g_rsqd);
            tdec = tanhf(sc);
            edec = __expf(sc);
        }
        float4 f[4]; float t[4];
        #pragma unroll
        for (int q = 0; q < 4; ++q) {
            int w = r0 + q * 32;
            f[q] = __ldg(reinterpret_cast<const float4*>(feat) + (size_t)w * 32 + lane);
            t[q] = __shfl_sync(0xFFFFFFFFu, tdec, q);
        }
        float esum = 0.0f;
        #pragma unroll
        for (int q = 0; q < 4; ++q) {
            int w = r0 + q * 32;
            float4 v = f[q];
            v.x *= t[q]; v.y *= t[q]; v.z *= t[q]; v.w *= t[q];
            reinterpret_cast<float4*>(out_full + (size_t)w * D_)[lane] = v;
        }
        if (lane < 4) {
            out_sm[r0 + lane * 32] = edec;   // exp(score); scaled later
            esum = edec;
        }
        // block sumexp -> one atomicAdd
        #pragma unroll
        for (int o = 16; o > 0; o >>= 1) esum += __shfl_xor_sync(0xFFFFFFFFu, esum, o);
        if ((tid & 31) == 0) sm[tid >> 5] = esum;
        __syncthreads();
        if (tid < 32) {
            float e2 = sm[tid];
            #pragma unroll
            for (int o = 16; o > 0; o >>= 1) e2 += __shfl_xor_sync(0xFFFFFFFFu, e2, o);
            if (tid == 0) atomicAdd(&g_sumexp, e2);
        }
        return;
    }

    // ---- sort path: decode scores from u64 state, then bitonic sort ----
    const int g    = blockIdx.x;
    const int base = g * N_;
    const int i0 = tid, i1 = tid + 1024;

    for (int i = tid; i < 256; i += 1024) rsqd_s[i] = g_rsqd[i];
    __syncthreads();

    unsigned long long k0, k1;
    {
        float s0 = decode_score(g_spu2[base + i0], bb, rsqd_s);
        float s1 = decode_score(g_spu2[base + i1], bb, rsqd_s);
        k0 = ((unsigned long long)(~ford(s0)) << 32) | (unsigned int)i0;
        k1 = ((unsigned long long)(~ford(s1)) << 32) | (unsigned int)i1;
    }

    // k = 2..32 entirely in registers
    #pragma unroll
    for (int k = 2; k <= 32; k <<= 1)
        for (int j = k >> 1; j >= 1; j >>= 1) { reg_ex(k0, i0, j, k); reg_ex(k1, i1, j, k); }

    // k = 64..2048: SMEM passes for j>=32, register passes for j<=16
    for (int k = 64; k <= N_; k <<= 1) {
        keys[i0] = k0; keys[i1] = k1;
        __syncthreads();
        for (int j = k >> 1; j >= 32; j >>= 1) {
            #pragma unroll
            for (int r = 0; r < 2; r++) {
                int i = tid + r * 1024;
                int ixj = i ^ j;
                if (ixj > i) {
                    unsigned long long a = keys[i], c = keys[ixj];
                    bool up = ((i & k) == 0);
                    if ((a > c) == up) { keys[i] = c; keys[ixj] = a; }
                }
            }
            __syncthreads();
        }
        k0 = keys[i0]; k1 = keys[i1];
        #pragma unroll
        for (int j = 16; j >= 1; j >>= 1) { reg_ex(k0, i0, j, k); reg_ex(k1, i1, j, k); }
    }
    keys[i0] = k0; keys[i1] = k1;
    __syncthreads();

    // flags: 1 = unselected
    flags[i0] = 1; flags[i1] = 1;
    __syncthreads();

    // top K_ = first 1024 sorted entries
    {
        int local = (int)(unsigned int)(keys[tid] & 0xFFFFFFFFull);
        flags[local] = 0;
        int gid = base + local;
        g_perm[g * K_ + tid]   = gid;
        out_perm[g * K_ + tid] = (float)gid;
    }
    __syncthreads();

    // warp-shfl scan over contiguous pairs
    {
        int e0 = 2 * tid, e1 = 2 * tid + 1;
        int f0 = flags[e0], f1 = flags[e1];
        int v = f0 + f1;
        int sv = v;
        #pragma unroll
        for (int o = 1; o < 32; o <<= 1) {
            int n = __shfl_up_sync(0xFFFFFFFFu, sv, o);
            if ((tid & 31) >= o) sv += n;
        }
        if ((tid & 31) == 31) woff[(tid >> 5) + 1] = sv;
        __syncthreads();
        if (tid == 0) {
            int run = 0;
            woff[0] = 0;
            #pragma unroll
            for (int wgi = 1; wgi <= 32; ++wgi) { run += woff[wgi]; woff[wgi] = run; }
        }
        __syncthreads();
        int pre = woff[tid >> 5] + (sv - v);
        if (f0) {
            int pos = g * (N_ - K_) + pre;
            g_permc[pos]      = base + e0;
            out_perm_com[pos] = (float)(base + e0);
        }
        if (f1) {
            int pos = g * (N_ - K_) + pre + f0;
            g_permc[pos]      = base + e1;
            out_perm_com[pos] = (float)(base + e1);
        }
    }
}

// dist/com = row copies from out_full (L2-warm), 4 rows per warp;
// prologue: scale out_sm slice by 1/g_sumexp.
__global__ __launch_bounds__(1024) void emitperm_kernel(const float* __restrict__ out_full,
                                                        float* __restrict__ out_dist,
                                                        float* __restrict__ out_com,
                                                        float* __restrict__ out_sm) {
    const int tid = threadIdx.x;
    // scale 128 out_sm elements per block
    if (tid < 128) {
        float inv = 1.0f / g_sumexp;
        int i = blockIdx.x * 128 + tid;
        out_sm[i] *= inv;
    }

    const int warp = tid >> 5, lane = tid & 31;
    const int r0 = blockIdx.x * 128 + warp;         // rows r0 + {0,32,64,96}

    float4 f[4]; float* o[4];
    #pragma unroll
    for (int q = 0; q < 4; ++q) {
        int r = r0 + q * 32;
        int p;
        if (r < BK_) {
            p = g_perm[r];
            o[q] = out_dist + (size_t)r * D_;
        } else {
            int rc = r - BK_;
            p = g_permc[rc];
            o[q] = out_com + (size_t)rc * D_;
        }
        f[q] = __ldg(reinterpret_cast<const float4*>(out_full) + (size_t)p * 32 + lane);
    }
    #pragma unroll
    for (int q = 0; q < 4; ++q)
        reinterpret_cast<float4*>(o[q])[lane] = f[q];
}

// ---------------- launch ----------------------------------------------------

extern "C" void kernel_launch(void* const* d_in, const int* in_sizes, int n_in,
                              void* d_out, int out_size) {
    const float* feature = (const float*)d_in[0];
    const float* W       = (const float*)d_in[1];
    const float* b       = (const float*)d_in[2];
    const int*   src     = (const int*)d_in[3];
    const int*   dst     = (const int*)d_in[4];

    float* out = (float*)d_out;
    float* out_dist     = out;                                  // BK_*D_
    float* out_com      = out + (size_t)BK_ * D_;               // BK_*D_
    float* out_full     = out + (size_t)2 * BK_ * D_;           // BN_*D_
    float* out_perm     = out + (size_t)2 * BK_ * D_ + (size_t)BN_ * D_;
    float* out_perm_com = out_perm + BK_;
    float* out_sm       = out_perm_com + BK_;

    init_kernel<<<(BN_ + 255) / 256, 256>>>();
    degdot_kernel<<<2 * NCTA_, 256>>>(src, feature, W);
    scatter_kernel<<<NCTA_, 256>>>(src, dst);
    sortemit_kernel<<<B_ + FULL_B_, 1024>>>(feature, b, out_perm, out_perm_com,
                                            out_full, out_sm);
    emitperm_kernel<<<PERM_B_, 1024>>>(out_full, out_dist, out_com, out_sm);
}